// round 1
// baseline (speedup 1.0000x reference)
#include <cuda_runtime.h>
#include <cuda_bf16.h>
#include <math.h>

// Problem constants (fixed by the dataset)
#define NN 100000          // nodes
#define EE 1600000         // edges
#define FF 128             // input feature dim
#define HH 256             // hidden dim
#define GG 512             // graphs
#define CC 10              // classes
#define L_REST 3
#define BN_EPS 1e-5f

// ---------------- device scratch (no allocations allowed) ----------------
__device__ float g_bufQ[NN * HH];   // agg output (h0)
__device__ float g_bufR[NN * HH];   // after first MLP GEMM (h1)
__device__ float g_bufP[NN * HH];   // layer output (h2) -> next layer input
__device__ int   g_rowptr[NN + 1];
__device__ int   g_col[EE];
__device__ int   g_deg[NN];         // degree counts, then reused as fill cursor
__device__ int   g_bsum[256];       // block sums for scan
__device__ float g_pooled[GG * HH];
__device__ float g_counts[GG];

// ---------------- utility kernels ----------------
__global__ void zero_i_kernel(int* p, int n) {
    int i = blockIdx.x * blockDim.x + threadIdx.x;
    if (i < n) p[i] = 0;
}
__global__ void zero_f_kernel(float* p, int n) {
    int i = blockIdx.x * blockDim.x + threadIdx.x;
    if (i < n) p[i] = 0.0f;
}

// ---------------- CSR build ----------------
__global__ void count_kernel(const int* __restrict__ dst, int* __restrict__ deg) {
    int e = blockIdx.x * blockDim.x + threadIdx.x;
    if (e < EE) atomicAdd(&deg[dst[e]], 1);
}

// exclusive scan, stage 1: per-block scan of deg -> rowptr (partial), block totals -> bsum
__global__ void scan1_kernel(const int* __restrict__ deg, int* __restrict__ rowptr,
                             int* __restrict__ bsum) {
    __shared__ int s[1024];
    int t = threadIdx.x;
    int idx = blockIdx.x * 1024 + t;
    int v = (idx < NN) ? deg[idx] : 0;
    s[t] = v;
    __syncthreads();
    for (int off = 1; off < 1024; off <<= 1) {
        int add = (t >= off) ? s[t - off] : 0;
        __syncthreads();
        s[t] += add;
        __syncthreads();
    }
    if (idx < NN) rowptr[idx] = s[t] - v;   // exclusive within block
    if (t == 1023) bsum[blockIdx.x] = s[t];
}

// stage 2: exclusive scan over block sums (single block, 128 threads, NB<=128)
__global__ void scan2_kernel(int* __restrict__ bsum, int nb) {
    __shared__ int s[128];
    int t = threadIdx.x;
    int v = (t < nb) ? bsum[t] : 0;
    s[t] = v;
    __syncthreads();
    for (int off = 1; off < 128; off <<= 1) {
        int add = (t >= off) ? s[t - off] : 0;
        __syncthreads();
        s[t] += add;
        __syncthreads();
    }
    if (t < nb) bsum[t] = s[t] - v;          // exclusive block offsets
}

// stage 3: add block offsets, set rowptr[NN]=EE
__global__ void scan3_kernel(int* __restrict__ rowptr, const int* __restrict__ bsum) {
    int idx = blockIdx.x * 1024 + threadIdx.x;
    if (idx < NN) rowptr[idx] += bsum[blockIdx.x];
    if (idx == 0) rowptr[NN] = EE;
}

__global__ void fill_kernel(const int* __restrict__ src, const int* __restrict__ dst,
                            const int* __restrict__ rowptr, int* __restrict__ cursor,
                            int* __restrict__ col) {
    int e = blockIdx.x * blockDim.x + threadIdx.x;
    if (e >= EE) return;
    int d = dst[e];
    int p = atomicAdd(&cursor[d], 1);
    col[rowptr[d] + p] = src[e];
}

// ---------------- neighbor sum-aggregate (CSR gather), fused h0 = x + agg ----------------
template <int HD>
__global__ void agg_kernel(const float* __restrict__ x, float* __restrict__ out,
                           const int* __restrict__ rowptr, const int* __restrict__ col) {
    int gw = (blockIdx.x * blockDim.x + threadIdx.x) >> 5;
    int lane = threadIdx.x & 31;
    if (gw >= NN) return;
    constexpr int V = HD / 128;   // float4 chunks per lane
    float4 acc[V];
#pragma unroll
    for (int v = 0; v < V; v++)
        acc[v] = *(const float4*)&x[(size_t)gw * HD + v * 128 + lane * 4];
    int s = rowptr[gw], e = rowptr[gw + 1];
    int j = s;
    for (; j + 1 < e; j += 2) {
        int nb0 = col[j], nb1 = col[j + 1];
        const float* r0 = &x[(size_t)nb0 * HD];
        const float* r1 = &x[(size_t)nb1 * HD];
#pragma unroll
        for (int v = 0; v < V; v++) {
            float4 t0 = *(const float4*)&r0[v * 128 + lane * 4];
            float4 t1 = *(const float4*)&r1[v * 128 + lane * 4];
            acc[v].x += t0.x + t1.x;
            acc[v].y += t0.y + t1.y;
            acc[v].z += t0.z + t1.z;
            acc[v].w += t0.w + t1.w;
        }
    }
    if (j < e) {
        int nb0 = col[j];
        const float* r0 = &x[(size_t)nb0 * HD];
#pragma unroll
        for (int v = 0; v < V; v++) {
            float4 t0 = *(const float4*)&r0[v * 128 + lane * 4];
            acc[v].x += t0.x; acc[v].y += t0.y; acc[v].z += t0.z; acc[v].w += t0.w;
        }
    }
#pragma unroll
    for (int v = 0; v < V; v++)
        *(float4*)&out[(size_t)gw * HD + v * 128 + lane * 4] = acc[v];
}

// ---------------- fp32 GEMM: C = epilogue(A[M,K] @ W[K,Nn] + bias) ----------------
// BM=128, BN=128, BK=16, 256 threads, 8x8 per thread, double-buffered smem.
template <bool DO_BN>
__global__ void __launch_bounds__(256) gemm_kernel(
    const float* __restrict__ A, const float* __restrict__ W,
    const float* __restrict__ bias, float* __restrict__ C,
    int M, int K, int Nn,
    const float* __restrict__ bn_g, const float* __restrict__ bn_b,
    const float* __restrict__ bn_rm, const float* __restrict__ bn_rv)
{
    __shared__ float As[2][16][128];
    __shared__ float Bs[2][16][128];
    const int tid = threadIdx.x;
    const int rowBlk = blockIdx.x * 128;
    const int colBlk = blockIdx.y * 128;
    const int tr = tid >> 4;       // 0..15
    const int tc = tid & 15;       // 0..15

    float acc[8][8];
#pragma unroll
    for (int i = 0; i < 8; i++)
#pragma unroll
        for (int jj = 0; jj < 8; jj++) acc[i][jj] = 0.0f;

    float4 aReg[2], bReg[2];
    const int nk = K / 16;

    // ---- load tile kb into regs ----
#define LOAD_TILE(kb)                                                              \
    {                                                                              \
        _Pragma("unroll")                                                          \
        for (int s = 0; s < 2; s++) {                                              \
            int i = tid + s * 256;                                                 \
            int r_ = i >> 2, c4 = i & 3;                                           \
            int grow = rowBlk + r_;                                                \
            if (grow < M)                                                          \
                aReg[s] = *(const float4*)&A[(size_t)grow * K + (kb) * 16 + c4 * 4]; \
            else                                                                   \
                aReg[s] = make_float4(0.f, 0.f, 0.f, 0.f);                         \
        }                                                                          \
        _Pragma("unroll")                                                          \
        for (int s = 0; s < 2; s++) {                                              \
            int i = tid + s * 256;                                                 \
            int r_ = i >> 5, c4 = i & 31;                                          \
            bReg[s] = *(const float4*)&W[(size_t)((kb) * 16 + r_) * Nn + colBlk + c4 * 4]; \
        }                                                                          \
    }

#define STORE_TILE(buf)                                                            \
    {                                                                              \
        _Pragma("unroll")                                                          \
        for (int s = 0; s < 2; s++) {                                              \
            int i = tid + s * 256;                                                 \
            int r_ = i >> 2, c4 = i & 3;                                           \
            As[buf][c4 * 4 + 0][r_] = aReg[s].x;                                   \
            As[buf][c4 * 4 + 1][r_] = aReg[s].y;                                   \
            As[buf][c4 * 4 + 2][r_] = aReg[s].z;                                   \
            As[buf][c4 * 4 + 3][r_] = aReg[s].w;                                   \
        }                                                                          \
        _Pragma("unroll")                                                          \
        for (int s = 0; s < 2; s++) {                                              \
            int i = tid + s * 256;                                                 \
            int r_ = i >> 5, c4 = i & 31;                                          \
            *(float4*)&Bs[buf][r_][c4 * 4] = bReg[s];                              \
        }                                                                          \
    }

    LOAD_TILE(0);
    STORE_TILE(0);
    __syncthreads();

    for (int kb = 0; kb < nk; kb++) {
        int cur = kb & 1;
        int nxt = cur ^ 1;
        if (kb + 1 < nk) LOAD_TILE(kb + 1);
#pragma unroll
        for (int k = 0; k < 16; k++) {
            float a[8], b[8];
            *(float4*)&a[0] = *(const float4*)&As[cur][k][tr * 8];
            *(float4*)&a[4] = *(const float4*)&As[cur][k][tr * 8 + 4];
            *(float4*)&b[0] = *(const float4*)&Bs[cur][k][tc * 8];
            *(float4*)&b[4] = *(const float4*)&Bs[cur][k][tc * 8 + 4];
#pragma unroll
            for (int i = 0; i < 8; i++)
#pragma unroll
                for (int jj = 0; jj < 8; jj++)
                    acc[i][jj] = fmaf(a[i], b[jj], acc[i][jj]);
        }
        if (kb + 1 < nk) {
            STORE_TILE(nxt);
            __syncthreads();
        }
    }

    // epilogue
    float bcol[8], scl[8], rmv[8], bev[8];
#pragma unroll
    for (int jj = 0; jj < 8; jj++) {
        int c = colBlk + tc * 8 + jj;
        bcol[jj] = bias[c];
        if (DO_BN) {
            scl[jj] = bn_g[c] * rsqrtf(bn_rv[c] + BN_EPS);
            rmv[jj] = bn_rm[c];
            bev[jj] = bn_b[c];
        }
    }
#pragma unroll
    for (int i = 0; i < 8; i++) {
        int row = rowBlk + tr * 8 + i;
        if (row >= M) continue;
        float v[8];
#pragma unroll
        for (int jj = 0; jj < 8; jj++) {
            float t = fmaxf(acc[i][jj] + bcol[jj], 0.0f);
            if (DO_BN) t = (t - rmv[jj]) * scl[jj] + bev[jj];
            v[jj] = t;
        }
        float* cp = &C[(size_t)row * Nn + colBlk + tc * 8];
        *(float4*)&cp[0] = *(float4*)&v[0];
        *(float4*)&cp[4] = *(float4*)&v[4];
    }
#undef LOAD_TILE
#undef STORE_TILE
}

// ---------------- pooling: batch is sorted -> tile 64 consecutive nodes per block ----------------
#define NODES_PER_BLK 64
__global__ void pool_kernel(const float* __restrict__ h, const int* __restrict__ batch,
                            float* __restrict__ pooled, float* __restrict__ counts) {
    int c = threadIdx.x;          // 0..255 feature column
    int n0 = blockIdx.x * NODES_PER_BLK;
    float sum = 0.0f;
    int cur = -1;
    for (int i = 0; i < NODES_PER_BLK; i++) {
        int n = n0 + i;
        if (n >= NN) break;
        int g = batch[n];
        if (g != cur) {
            if (cur >= 0) atomicAdd(&pooled[(size_t)cur * HH + c], sum);
            sum = 0.0f;
            cur = g;
        }
        sum += h[(size_t)n * HH + c];
    }
    if (cur >= 0) atomicAdd(&pooled[(size_t)cur * HH + c], sum);

    if (c == 0) {
        float cnt = 0.0f;
        int cg = -1;
        for (int i = 0; i < NODES_PER_BLK; i++) {
            int n = n0 + i;
            if (n >= NN) break;
            int g = batch[n];
            if (g != cg) {
                if (cg >= 0) atomicAdd(&counts[cg], cnt);
                cnt = 0.0f;
                cg = g;
            }
            cnt += 1.0f;
        }
        if (cg >= 0) atomicAdd(&counts[cg], cnt);
    }
}

// ---------------- head: mean -> relu(Wf) -> Wo -> log_softmax ----------------
__global__ void head_kernel(const float* __restrict__ pooled, const float* __restrict__ counts,
                            const float* __restrict__ Wf, const float* __restrict__ bf,
                            const float* __restrict__ Wo, const float* __restrict__ bo,
                            float* __restrict__ out) {
    __shared__ float sp[HH];
    __shared__ float sh[HH];
    __shared__ float sl[CC];
    int g = blockIdx.x;
    int t = threadIdx.x;
    float cnt = fmaxf(counts[g], 1.0f);
    sp[t] = pooled[(size_t)g * HH + t] / cnt;
    __syncthreads();
    float acc = bf[t];
#pragma unroll 8
    for (int k = 0; k < HH; k++)
        acc = fmaf(sp[k], Wf[(size_t)k * HH + t], acc);
    sh[t] = fmaxf(acc, 0.0f);
    __syncthreads();
    if (t < CC) {
        float a = bo[t];
        for (int k = 0; k < HH; k++)
            a = fmaf(sh[k], Wo[(size_t)k * CC + t], a);
        sl[t] = a;
    }
    __syncthreads();
    if (t == 0) {
        float mx = -1e30f;
        for (int c = 0; c < CC; c++) mx = fmaxf(mx, sl[c]);
        float s = 0.0f;
        for (int c = 0; c < CC; c++) s += expf(sl[c] - mx);
        float lse = mx + logf(s);
        for (int c = 0; c < CC; c++) out[(size_t)g * CC + c] = sl[c] - lse;
    }
}

// ---------------- launch ----------------
extern "C" void kernel_launch(void* const* d_in, const int* in_sizes, int n_in,
                              void* d_out, int out_size) {
    const float* x    = (const float*)d_in[0];
    const int*   ei   = (const int*)d_in[1];
    const int*   src  = ei;
    const int*   dst  = ei + EE;
    const int*   batch= (const int*)d_in[2];
    const float* W1a  = (const float*)d_in[3];
    const float* b1a  = (const float*)d_in[4];
    const float* W2a  = (const float*)d_in[5];
    const float* b2a  = (const float*)d_in[6];
    const float* g_a  = (const float*)d_in[7];
    const float* be_a = (const float*)d_in[8];
    const float* rm_a = (const float*)d_in[9];
    const float* rv_a = (const float*)d_in[10];
    const float* Ws1  = (const float*)d_in[11];
    const float* bs1  = (const float*)d_in[12];
    const float* Ws2  = (const float*)d_in[13];
    const float* bs2  = (const float*)d_in[14];
    const float* gs   = (const float*)d_in[15];
    const float* bes  = (const float*)d_in[16];
    const float* rms  = (const float*)d_in[17];
    const float* rvs  = (const float*)d_in[18];
    const float* Wf   = (const float*)d_in[19];
    const float* bf   = (const float*)d_in[20];
    const float* Wo   = (const float*)d_in[21];
    const float* bo   = (const float*)d_in[22];
    float* out = (float*)d_out;

    float *bufQ, *bufR, *bufP, *pooled, *counts;
    int *rowptr, *col, *deg, *bsum;
    cudaGetSymbolAddress((void**)&bufQ, g_bufQ);
    cudaGetSymbolAddress((void**)&bufR, g_bufR);
    cudaGetSymbolAddress((void**)&bufP, g_bufP);
    cudaGetSymbolAddress((void**)&rowptr, g_rowptr);
    cudaGetSymbolAddress((void**)&col, g_col);
    cudaGetSymbolAddress((void**)&deg, g_deg);
    cudaGetSymbolAddress((void**)&bsum, g_bsum);
    cudaGetSymbolAddress((void**)&pooled, g_pooled);
    cudaGetSymbolAddress((void**)&counts, g_counts);

    const int NB = (NN + 1023) / 1024;   // 98 scan blocks

    // ---- CSR build ----
    zero_i_kernel<<<(NN + 255) / 256, 256>>>(deg, NN);
    count_kernel<<<(EE + 255) / 256, 256>>>(dst, deg);
    scan1_kernel<<<NB, 1024>>>(deg, rowptr, bsum);
    scan2_kernel<<<1, 128>>>(bsum, NB);
    scan3_kernel<<<NB, 1024>>>(rowptr, bsum);
    zero_i_kernel<<<(NN + 255) / 256, 256>>>(deg, NN);   // reuse as cursor
    fill_kernel<<<(EE + 255) / 256, 256>>>(src, dst, rowptr, deg, col);

    dim3 ggrid((NN + 127) / 128, HH / 128);
    const int aggBlocks = (NN * 32 + 255) / 256;

    // ---- layer 1 (F=128 -> H=256) ----
    agg_kernel<FF><<<aggBlocks, 256>>>(x, bufQ, rowptr, col);
    gemm_kernel<false><<<ggrid, 256>>>(bufQ, W1a, b1a, bufR, NN, FF, HH,
                                       nullptr, nullptr, nullptr, nullptr);
    gemm_kernel<true><<<ggrid, 256>>>(bufR, W2a, b2a, bufP, NN, HH, HH,
                                      g_a, be_a, rm_a, rv_a);

    // ---- layers 2..4 ----
    for (int l = 0; l < L_REST; l++) {
        agg_kernel<HH><<<aggBlocks, 256>>>(bufP, bufQ, rowptr, col);
        gemm_kernel<false><<<ggrid, 256>>>(bufQ, Ws1 + (size_t)l * HH * HH, bs1 + l * HH,
                                           bufR, NN, HH, HH,
                                           nullptr, nullptr, nullptr, nullptr);
        gemm_kernel<true><<<ggrid, 256>>>(bufR, Ws2 + (size_t)l * HH * HH, bs2 + l * HH,
                                          bufP, NN, HH, HH,
                                          gs + l * HH, bes + l * HH, rms + l * HH, rvs + l * HH);
    }

    // ---- pooling ----
    zero_f_kernel<<<(GG * HH + 255) / 256, 256>>>(pooled, GG * HH);
    zero_f_kernel<<<(GG + 255) / 256, 256>>>(counts, GG);
    pool_kernel<<<(NN + NODES_PER_BLK - 1) / NODES_PER_BLK, HH>>>(bufP, batch, pooled, counts);

    // ---- head ----
    head_kernel<<<GG, HH>>>(pooled, counts, Wf, bf, Wo, bo, out);
}

// round 3
// speedup vs baseline: 2.3886x; 2.3886x over previous
#include <cuda_runtime.h>
#include <cuda_bf16.h>
#include <stdint.h>
#include <math.h>

// Problem constants (fixed by the dataset)
#define NN 100000          // nodes
#define EE 1600000         // edges
#define FF 128             // input feature dim
#define HH 256             // hidden dim
#define GG 512             // graphs
#define CC 10              // classes
#define L_REST 3
#define BN_EPS 1e-5f

// ---------------- device scratch (no allocations allowed) ----------------
__device__ float g_bufQ[NN * HH];   // agg output (h0)
__device__ float g_bufR[NN * HH];   // after first MLP GEMM (h1)
__device__ float g_bufP[NN * HH];   // layer output (h2) -> next layer input
__device__ int   g_rowptr[NN + 1];
__device__ int   g_col[EE];
__device__ int   g_deg[NN];         // degree counts, then reused as fill cursor
__device__ int   g_bsum[256];       // block sums for scan
__device__ float g_pooled[GG * HH];
__device__ float g_counts[GG];

// ---------------- utility kernels ----------------
__global__ void zero_i_kernel(int* p, int n) {
    int i = blockIdx.x * blockDim.x + threadIdx.x;
    if (i < n) p[i] = 0;
}
__global__ void zero_f_kernel(float* p, int n) {
    int i = blockIdx.x * blockDim.x + threadIdx.x;
    if (i < n) p[i] = 0.0f;
}

// ---------------- CSR build ----------------
__global__ void count_kernel(const int* __restrict__ dst, int* __restrict__ deg) {
    int e = blockIdx.x * blockDim.x + threadIdx.x;
    if (e < EE) atomicAdd(&deg[dst[e]], 1);
}

__global__ void scan1_kernel(const int* __restrict__ deg, int* __restrict__ rowptr,
                             int* __restrict__ bsum) {
    __shared__ int s[1024];
    int t = threadIdx.x;
    int idx = blockIdx.x * 1024 + t;
    int v = (idx < NN) ? deg[idx] : 0;
    s[t] = v;
    __syncthreads();
    for (int off = 1; off < 1024; off <<= 1) {
        int add = (t >= off) ? s[t - off] : 0;
        __syncthreads();
        s[t] += add;
        __syncthreads();
    }
    if (idx < NN) rowptr[idx] = s[t] - v;
    if (t == 1023) bsum[blockIdx.x] = s[t];
}

__global__ void scan2_kernel(int* __restrict__ bsum, int nb) {
    __shared__ int s[128];
    int t = threadIdx.x;
    int v = (t < nb) ? bsum[t] : 0;
    s[t] = v;
    __syncthreads();
    for (int off = 1; off < 128; off <<= 1) {
        int add = (t >= off) ? s[t - off] : 0;
        __syncthreads();
        s[t] += add;
        __syncthreads();
    }
    if (t < nb) bsum[t] = s[t] - v;
}

__global__ void scan3_kernel(int* __restrict__ rowptr, const int* __restrict__ bsum) {
    int idx = blockIdx.x * 1024 + threadIdx.x;
    if (idx < NN) rowptr[idx] += bsum[blockIdx.x];
    if (idx == 0) rowptr[NN] = EE;
}

__global__ void fill_kernel(const int* __restrict__ src, const int* __restrict__ dst,
                            const int* __restrict__ rowptr, int* __restrict__ cursor,
                            int* __restrict__ col) {
    int e = blockIdx.x * blockDim.x + threadIdx.x;
    if (e >= EE) return;
    int d = dst[e];
    int p = atomicAdd(&cursor[d], 1);
    col[rowptr[d] + p] = src[e];
}

// ---------------- neighbor sum-aggregate (CSR gather), fused h0 = x + agg ----------------
template <int HD>
__global__ void agg_kernel(const float* __restrict__ x, float* __restrict__ out,
                           const int* __restrict__ rowptr, const int* __restrict__ col) {
    int gw = (blockIdx.x * blockDim.x + threadIdx.x) >> 5;
    int lane = threadIdx.x & 31;
    if (gw >= NN) return;
    constexpr int V = HD / 128;
    float4 acc[V];
#pragma unroll
    for (int v = 0; v < V; v++)
        acc[v] = *(const float4*)&x[(size_t)gw * HD + v * 128 + lane * 4];
    int s = rowptr[gw], e = rowptr[gw + 1];
    int j = s;
    for (; j + 1 < e; j += 2) {
        int nb0 = col[j], nb1 = col[j + 1];
        const float* r0 = &x[(size_t)nb0 * HD];
        const float* r1 = &x[(size_t)nb1 * HD];
#pragma unroll
        for (int v = 0; v < V; v++) {
            float4 t0 = *(const float4*)&r0[v * 128 + lane * 4];
            float4 t1 = *(const float4*)&r1[v * 128 + lane * 4];
            acc[v].x += t0.x + t1.x;
            acc[v].y += t0.y + t1.y;
            acc[v].z += t0.z + t1.z;
            acc[v].w += t0.w + t1.w;
        }
    }
    if (j < e) {
        int nb0 = col[j];
        const float* r0 = &x[(size_t)nb0 * HD];
#pragma unroll
        for (int v = 0; v < V; v++) {
            float4 t0 = *(const float4*)&r0[v * 128 + lane * 4];
            acc[v].x += t0.x; acc[v].y += t0.y; acc[v].z += t0.z; acc[v].w += t0.w;
        }
    }
#pragma unroll
    for (int v = 0; v < V; v++)
        *(float4*)&out[(size_t)gw * HD + v * 128 + lane * 4] = acc[v];
}

// ---------------- tf32 tensor-core GEMM ----------------
// C = epilogue(A[M,K] @ W[K,Nn] + bias), BM=128, BN=128, BK=16, 256 threads.
// Warp tile 64x32 (4x4 mma m16n8k8 tiles), cp.async double buffered.
// A smem stride 20 floats, B smem stride 132 floats -> conflict-free mma reads.

#define ASTRIDE 20
#define BSTRIDE 132

__device__ __forceinline__ uint32_t f2tf32(float x) {
    uint32_t r;
    asm("cvt.rna.tf32.f32 %0, %1;" : "=r"(r) : "f"(x));
    return r;
}

__device__ __forceinline__ void mma_tf32(float c[4], const uint32_t a[4], const uint32_t b[2]) {
    asm volatile(
        "mma.sync.aligned.m16n8k8.row.col.f32.tf32.tf32.f32 "
        "{%0,%1,%2,%3}, {%4,%5,%6,%7}, {%8,%9}, {%0,%1,%2,%3};\n"
        : "+f"(c[0]), "+f"(c[1]), "+f"(c[2]), "+f"(c[3])
        : "r"(a[0]), "r"(a[1]), "r"(a[2]), "r"(a[3]), "r"(b[0]), "r"(b[1]));
}

#define CP_ASYNC16(dst_u32, src_ptr, sz) \
    asm volatile("cp.async.cg.shared.global [%0], [%1], 16, %2;\n" \
                 :: "r"(dst_u32), "l"(src_ptr), "r"(sz))

template <bool DO_BN>
__global__ void __launch_bounds__(256) gemm_tc_kernel(
    const float* __restrict__ A, const float* __restrict__ W,
    const float* __restrict__ bias, float* __restrict__ C,
    int M, int K, int Nn,
    const float* __restrict__ bn_g, const float* __restrict__ bn_b,
    const float* __restrict__ bn_rm, const float* __restrict__ bn_rv)
{
    __shared__ float As[2][128 * ASTRIDE];   // 20 KB
    __shared__ float Bs[2][16 * BSTRIDE];    // 16.9 KB

    const int tid = threadIdx.x;
    const int lane = tid & 31;
    const int wid = tid >> 5;
    const int wr = wid & 1;          // warp row (0..1) -> 64 rows each
    const int wc = wid >> 1;         // warp col (0..3) -> 32 cols each
    const int rowBlk = blockIdx.x * 128;
    const int colBlk = blockIdx.y * 128;
    const int nk = K >> 4;

    // ---- per-thread load maps (2 float4 of A, 2 float4 of B per tile) ----
    int arow[2], acol[2], aSmOff[2], aSz[2];
    const float* aPtr0[2];
    int brow[2], bcol[2], bSmOff[2];
    const float* bPtr0[2];
#pragma unroll
    for (int s = 0; s < 2; s++) {
        int i = tid + s * 256;
        arow[s] = i >> 2;
        acol[s] = (i & 3) * 4;
        aSmOff[s] = arow[s] * ASTRIDE + acol[s];
        int grow = rowBlk + arow[s];
        bool v = grow < M;
        aSz[s] = v ? 16 : 0;
        aPtr0[s] = A + (size_t)(v ? grow : 0) * K + acol[s];

        brow[s] = i >> 5;
        bcol[s] = (i & 31) * 4;
        bSmOff[s] = brow[s] * BSTRIDE + bcol[s];
        bPtr0[s] = W + (size_t)brow[s] * Nn + colBlk + bcol[s];
    }
    uint32_t asBase[2], bsBase[2];
#pragma unroll
    for (int b = 0; b < 2; b++) {
        asBase[b] = (uint32_t)__cvta_generic_to_shared(&As[b][0]);
        bsBase[b] = (uint32_t)__cvta_generic_to_shared(&Bs[b][0]);
    }

    float acc[4][4][4];
#pragma unroll
    for (int mt = 0; mt < 4; mt++)
#pragma unroll
        for (int nt = 0; nt < 4; nt++)
#pragma unroll
            for (int q = 0; q < 4; q++) acc[mt][nt][q] = 0.0f;

    // ---- prologue: load tile 0 ----
#pragma unroll
    for (int s = 0; s < 2; s++)
        CP_ASYNC16(asBase[0] + aSmOff[s] * 4, aPtr0[s], aSz[s]);
#pragma unroll
    for (int s = 0; s < 2; s++)
        CP_ASYNC16(bsBase[0] + bSmOff[s] * 4, bPtr0[s], 16);
    asm volatile("cp.async.commit_group;\n");

    for (int kb = 0; kb < nk; kb++) {
        int cur = kb & 1;
        if (kb + 1 < nk) {
            int nxt = cur ^ 1;
#pragma unroll
            for (int s = 0; s < 2; s++)
                CP_ASYNC16(asBase[nxt] + aSmOff[s] * 4, aPtr0[s] + (kb + 1) * 16, aSz[s]);
#pragma unroll
            for (int s = 0; s < 2; s++)
                CP_ASYNC16(bsBase[nxt] + bSmOff[s] * 4, bPtr0[s] + (size_t)(kb + 1) * 16 * Nn, 16);
            asm volatile("cp.async.commit_group;\n");
            asm volatile("cp.async.wait_group 1;\n");
        } else {
            asm volatile("cp.async.wait_group 0;\n");
        }
        __syncthreads();

        const float* as = &As[cur][0];
        const float* bs = &Bs[cur][0];
#pragma unroll
        for (int ks = 0; ks < 2; ks++) {
            uint32_t afr[4][4];
#pragma unroll
            for (int mt = 0; mt < 4; mt++) {
                int r0 = wr * 64 + mt * 16 + (lane >> 2);
                int c0 = ks * 8 + (lane & 3);
                afr[mt][0] = f2tf32(as[r0 * ASTRIDE + c0]);
                afr[mt][1] = f2tf32(as[(r0 + 8) * ASTRIDE + c0]);
                afr[mt][2] = f2tf32(as[r0 * ASTRIDE + c0 + 4]);
                afr[mt][3] = f2tf32(as[(r0 + 8) * ASTRIDE + c0 + 4]);
            }
            uint32_t bfr[4][2];
#pragma unroll
            for (int nt = 0; nt < 4; nt++) {
                int kk = ks * 8 + (lane & 3);
                int cn = wc * 32 + nt * 8 + (lane >> 2);
                bfr[nt][0] = f2tf32(bs[kk * BSTRIDE + cn]);
                bfr[nt][1] = f2tf32(bs[(kk + 4) * BSTRIDE + cn]);
            }
#pragma unroll
            for (int mt = 0; mt < 4; mt++)
#pragma unroll
                for (int nt = 0; nt < 4; nt++)
                    mma_tf32(acc[mt][nt], afr[mt], bfr[nt]);
        }
        __syncthreads();
    }

    // ---- epilogue: bias + relu (+ BN), write C ----
#pragma unroll
    for (int nt = 0; nt < 4; nt++) {
        int c0 = colBlk + wc * 32 + nt * 8 + 2 * (lane & 3);
        float bb0 = bias[c0], bb1 = bias[c0 + 1];
        float s0 = 0.f, s1 = 0.f, m0 = 0.f, m1 = 0.f, e0 = 0.f, e1 = 0.f;
        if (DO_BN) {
            s0 = bn_g[c0] * rsqrtf(bn_rv[c0] + BN_EPS);
            s1 = bn_g[c0 + 1] * rsqrtf(bn_rv[c0 + 1] + BN_EPS);
            m0 = bn_rm[c0]; m1 = bn_rm[c0 + 1];
            e0 = bn_b[c0];  e1 = bn_b[c0 + 1];
        }
#pragma unroll
        for (int mt = 0; mt < 4; mt++) {
            int r = rowBlk + wr * 64 + mt * 16 + (lane >> 2);
            float v0 = fmaxf(acc[mt][nt][0] + bb0, 0.0f);
            float v1 = fmaxf(acc[mt][nt][1] + bb1, 0.0f);
            float v2 = fmaxf(acc[mt][nt][2] + bb0, 0.0f);
            float v3 = fmaxf(acc[mt][nt][3] + bb1, 0.0f);
            if (DO_BN) {
                v0 = (v0 - m0) * s0 + e0;
                v1 = (v1 - m1) * s1 + e1;
                v2 = (v2 - m0) * s0 + e0;
                v3 = (v3 - m1) * s1 + e1;
            }
            if (r < M)     *(float2*)&C[(size_t)r * Nn + c0]       = make_float2(v0, v1);
            if (r + 8 < M) *(float2*)&C[(size_t)(r + 8) * Nn + c0] = make_float2(v2, v3);
        }
    }
}

// ---------------- pooling ----------------
#define NODES_PER_BLK 64
__global__ void pool_kernel(const float* __restrict__ h, const int* __restrict__ batch,
                            float* __restrict__ pooled, float* __restrict__ counts) {
    int c = threadIdx.x;
    int n0 = blockIdx.x * NODES_PER_BLK;
    float sum = 0.0f;
    int cur = -1;
    for (int i = 0; i < NODES_PER_BLK; i++) {
        int n = n0 + i;
        if (n >= NN) break;
        int g = batch[n];
        if (g != cur) {
            if (cur >= 0) atomicAdd(&pooled[(size_t)cur * HH + c], sum);
            sum = 0.0f;
            cur = g;
        }
        sum += h[(size_t)n * HH + c];
    }
    if (cur >= 0) atomicAdd(&pooled[(size_t)cur * HH + c], sum);

    if (c == 0) {
        float cnt = 0.0f;
        int cg = -1;
        for (int i = 0; i < NODES_PER_BLK; i++) {
            int n = n0 + i;
            if (n >= NN) break;
            int g = batch[n];
            if (g != cg) {
                if (cg >= 0) atomicAdd(&counts[cg], cnt);
                cnt = 0.0f;
                cg = g;
            }
            cnt += 1.0f;
        }
        if (cg >= 0) atomicAdd(&counts[cg], cnt);
    }
}

// ---------------- head ----------------
__global__ void head_kernel(const float* __restrict__ pooled, const float* __restrict__ counts,
                            const float* __restrict__ Wf, const float* __restrict__ bf,
                            const float* __restrict__ Wo, const float* __restrict__ bo,
                            float* __restrict__ out) {
    __shared__ float sp[HH];
    __shared__ float sh[HH];
    __shared__ float sl[CC];
    int g = blockIdx.x;
    int t = threadIdx.x;
    float cnt = fmaxf(counts[g], 1.0f);
    sp[t] = pooled[(size_t)g * HH + t] / cnt;
    __syncthreads();
    float acc = bf[t];
#pragma unroll 8
    for (int k = 0; k < HH; k++)
        acc = fmaf(sp[k], Wf[(size_t)k * HH + t], acc);
    sh[t] = fmaxf(acc, 0.0f);
    __syncthreads();
    if (t < CC) {
        float a = bo[t];
        for (int k = 0; k < HH; k++)
            a = fmaf(sh[k], Wo[(size_t)k * CC + t], a);
        sl[t] = a;
    }
    __syncthreads();
    if (t == 0) {
        float mx = -1e30f;
        for (int c = 0; c < CC; c++) mx = fmaxf(mx, sl[c]);
        float s = 0.0f;
        for (int c = 0; c < CC; c++) s += expf(sl[c] - mx);
        float lse = mx + logf(s);
        for (int c = 0; c < CC; c++) out[(size_t)g * CC + c] = sl[c] - lse;
    }
}

// ---------------- launch ----------------
extern "C" void kernel_launch(void* const* d_in, const int* in_sizes, int n_in,
                              void* d_out, int out_size) {
    const float* x    = (const float*)d_in[0];
    const int*   ei   = (const int*)d_in[1];
    const int*   src  = ei;
    const int*   dst  = ei + EE;
    const int*   batch= (const int*)d_in[2];
    const float* W1a  = (const float*)d_in[3];
    const float* b1a  = (const float*)d_in[4];
    const float* W2a  = (const float*)d_in[5];
    const float* b2a  = (const float*)d_in[6];
    const float* g_a  = (const float*)d_in[7];
    const float* be_a = (const float*)d_in[8];
    const float* rm_a = (const float*)d_in[9];
    const float* rv_a = (const float*)d_in[10];
    const float* Ws1  = (const float*)d_in[11];
    const float* bs1  = (const float*)d_in[12];
    const float* Ws2  = (const float*)d_in[13];
    const float* bs2  = (const float*)d_in[14];
    const float* gs   = (const float*)d_in[15];
    const float* bes  = (const float*)d_in[16];
    const float* rms  = (const float*)d_in[17];
    const float* rvs  = (const float*)d_in[18];
    const float* Wf   = (const float*)d_in[19];
    const float* bf   = (const float*)d_in[20];
    const float* Wo   = (const float*)d_in[21];
    const float* bo   = (const float*)d_in[22];
    float* out = (float*)d_out;

    float *bufQ, *bufR, *bufP, *pooled, *counts;
    int *rowptr, *col, *deg, *bsum;
    cudaGetSymbolAddress((void**)&bufQ, g_bufQ);
    cudaGetSymbolAddress((void**)&bufR, g_bufR);
    cudaGetSymbolAddress((void**)&bufP, g_bufP);
    cudaGetSymbolAddress((void**)&rowptr, g_rowptr);
    cudaGetSymbolAddress((void**)&col, g_col);
    cudaGetSymbolAddress((void**)&deg, g_deg);
    cudaGetSymbolAddress((void**)&bsum, g_bsum);
    cudaGetSymbolAddress((void**)&pooled, g_pooled);
    cudaGetSymbolAddress((void**)&counts, g_counts);

    const int NB = (NN + 1023) / 1024;

    // ---- CSR build ----
    zero_i_kernel<<<(NN + 255) / 256, 256>>>(deg, NN);
    count_kernel<<<(EE + 255) / 256, 256>>>(dst, deg);
    scan1_kernel<<<NB, 1024>>>(deg, rowptr, bsum);
    scan2_kernel<<<1, 128>>>(bsum, NB);
    scan3_kernel<<<NB, 1024>>>(rowptr, bsum);
    zero_i_kernel<<<(NN + 255) / 256, 256>>>(deg, NN);
    fill_kernel<<<(EE + 255) / 256, 256>>>(src, dst, rowptr, deg, col);

    dim3 ggrid((NN + 127) / 128, HH / 128);
    const int aggBlocks = (NN * 32 + 255) / 256;

    // ---- layer 1 (F=128 -> H=256) ----
    agg_kernel<FF><<<aggBlocks, 256>>>(x, bufQ, rowptr, col);
    gemm_tc_kernel<false><<<ggrid, 256>>>(bufQ, W1a, b1a, bufR, NN, FF, HH,
                                          nullptr, nullptr, nullptr, nullptr);
    gemm_tc_kernel<true><<<ggrid, 256>>>(bufR, W2a, b2a, bufP, NN, HH, HH,
                                         g_a, be_a, rm_a, rv_a);

    // ---- layers 2..4 ----
    for (int l = 0; l < L_REST; l++) {
        agg_kernel<HH><<<aggBlocks, 256>>>(bufP, bufQ, rowptr, col);
        gemm_tc_kernel<false><<<ggrid, 256>>>(bufQ, Ws1 + (size_t)l * HH * HH, bs1 + l * HH,
                                              bufR, NN, HH, HH,
                                              nullptr, nullptr, nullptr, nullptr);
        gemm_tc_kernel<true><<<ggrid, 256>>>(bufR, Ws2 + (size_t)l * HH * HH, bs2 + l * HH,
                                             bufP, NN, HH, HH,
                                             gs + l * HH, bes + l * HH, rms + l * HH, rvs + l * HH);
    }

    // ---- pooling ----
    zero_f_kernel<<<(GG * HH + 255) / 256, 256>>>(pooled, GG * HH);
    zero_f_kernel<<<(GG + 255) / 256, 256>>>(counts, GG);
    pool_kernel<<<(NN + NODES_PER_BLK - 1) / NODES_PER_BLK, HH>>>(bufP, batch, pooled, counts);

    // ---- head ----
    head_kernel<<<GG, HH>>>(pooled, counts, Wf, bf, Wo, bo, out);
}

// round 5
// speedup vs baseline: 2.3979x; 1.0039x over previous
#include <cuda_runtime.h>
#include <cuda_bf16.h>
#include <stdint.h>
#include <math.h>

// Problem constants (fixed by the dataset)
#define NN 100000          // nodes
#define EE 1600000         // edges
#define FF 128             // input feature dim
#define HH 256             // hidden dim
#define GG 512             // graphs
#define CC 10              // classes
#define L_REST 3
#define BN_EPS 1e-5f

// ---------------- device scratch (no allocations allowed) ----------------
__device__ float g_bufQ[NN * HH];            // agg output (h0)
__device__ float g_bufR[NN * HH];            // after first MLP GEMM (h1)
__device__ float g_bufP[NN * HH];            // layer output (h2) -> next layer input
__device__ __nv_bfloat16 g_bufB[NN * HH];    // bf16 shadow of current features (gather source)
__device__ int   g_rowptr[NN + 1];
__device__ int   g_col[EE];
__device__ int   g_deg[NN];
__device__ int   g_bsum[256];
__device__ float g_pooled[GG * HH];
__device__ float g_counts[GG];

// ---------------- utility kernels ----------------
__global__ void zero_i_kernel(int* p, int n) {
    int i = blockIdx.x * blockDim.x + threadIdx.x;
    if (i < n) p[i] = 0;
}
__global__ void zero_f_kernel(float* p, int n) {
    int i = blockIdx.x * blockDim.x + threadIdx.x;
    if (i < n) p[i] = 0.0f;
}
// fp32 -> bf16 vectorized convert (n4 = count/4)
__global__ void f2b_kernel(const float* __restrict__ in, __nv_bfloat16* __restrict__ out, int n4) {
    int i = blockIdx.x * blockDim.x + threadIdx.x;
    if (i >= n4) return;
    float4 v = ((const float4*)in)[i];
    __nv_bfloat162 a = __floats2bfloat162_rn(v.x, v.y);
    __nv_bfloat162 b = __floats2bfloat162_rn(v.z, v.w);
    uint2 o;
    o.x = *(uint32_t*)&a;
    o.y = *(uint32_t*)&b;
    ((uint2*)out)[i] = o;
}

// ---------------- CSR build ----------------
__global__ void count_kernel(const int* __restrict__ dst, int* __restrict__ deg) {
    int e = blockIdx.x * blockDim.x + threadIdx.x;
    if (e < EE) atomicAdd(&deg[dst[e]], 1);
}

__global__ void scan1_kernel(const int* __restrict__ deg, int* __restrict__ rowptr,
                             int* __restrict__ bsum) {
    __shared__ int s[1024];
    int t = threadIdx.x;
    int idx = blockIdx.x * 1024 + t;
    int v = (idx < NN) ? deg[idx] : 0;
    s[t] = v;
    __syncthreads();
    for (int off = 1; off < 1024; off <<= 1) {
        int add = (t >= off) ? s[t - off] : 0;
        __syncthreads();
        s[t] += add;
        __syncthreads();
    }
    if (idx < NN) rowptr[idx] = s[t] - v;
    if (t == 1023) bsum[blockIdx.x] = s[t];
}

__global__ void scan2_kernel(int* __restrict__ bsum, int nb) {
    __shared__ int s[128];
    int t = threadIdx.x;
    int v = (t < nb) ? bsum[t] : 0;
    s[t] = v;
    __syncthreads();
    for (int off = 1; off < 128; off <<= 1) {
        int add = (t >= off) ? s[t - off] : 0;
        __syncthreads();
        s[t] += add;
        __syncthreads();
    }
    if (t < nb) bsum[t] = s[t] - v;
}

__global__ void scan3_kernel(int* __restrict__ rowptr, const int* __restrict__ bsum) {
    int idx = blockIdx.x * 1024 + threadIdx.x;
    if (idx < NN) rowptr[idx] += bsum[blockIdx.x];
    if (idx == 0) rowptr[NN] = EE;
}

__global__ void fill_kernel(const int* __restrict__ src, const int* __restrict__ dst,
                            const int* __restrict__ rowptr, int* __restrict__ cursor,
                            int* __restrict__ col) {
    int e = blockIdx.x * blockDim.x + threadIdx.x;
    if (e >= EE) return;
    int d = dst[e];
    int p = atomicAdd(&cursor[d], 1);
    col[rowptr[d] + p] = src[e];
}

// ---------------- neighbor sum-aggregate, bf16 gather + fp32 self/accum ----------------
// out[n] = xs[n] + sum_{nb} xb[nb]   (one warp per node)
template <int HD>
__global__ void aggb_kernel(const float* __restrict__ xs, const __nv_bfloat16* __restrict__ xb,
                            float* __restrict__ out,
                            const int* __restrict__ rowptr, const int* __restrict__ col) {
    int gw = (blockIdx.x * blockDim.x + threadIdx.x) >> 5;
    int lane = threadIdx.x & 31;
    if (gw >= NN) return;
    constexpr int P = HD / 32;            // bf16 elems per lane (8 for HD=256, 4 for HD=128)
    float acc[P];
    const float* selfp = &xs[(size_t)gw * HD + lane * P];
#pragma unroll
    for (int v = 0; v < P; v += 4) {
        float4 t = *(const float4*)&selfp[v];
        acc[v] = t.x; acc[v + 1] = t.y; acc[v + 2] = t.z; acc[v + 3] = t.w;
    }
    int s = rowptr[gw], e = rowptr[gw + 1];
    int j = s;

    auto addrow = [&](int nb) {
        const __nv_bfloat16* r = &xb[(size_t)nb * HD + lane * P];
        if constexpr (P == 8) {
            uint4 u = *(const uint4*)r;
            uint32_t w[4] = {u.x, u.y, u.z, u.w};
#pragma unroll
            for (int q = 0; q < 4; q++) {
                float2 f = __bfloat1622float2(*(const __nv_bfloat162*)&w[q]);
                acc[q * 2] += f.x;
                acc[q * 2 + 1] += f.y;
            }
        } else {
            uint2 u = *(const uint2*)r;
            uint32_t w[2] = {u.x, u.y};
#pragma unroll
            for (int q = 0; q < 2; q++) {
                float2 f = __bfloat1622float2(*(const __nv_bfloat162*)&w[q]);
                acc[q * 2] += f.x;
                acc[q * 2 + 1] += f.y;
            }
        }
    };

    for (; j + 3 < e; j += 4) {
        int n0 = col[j], n1 = col[j + 1], n2 = col[j + 2], n3 = col[j + 3];
        addrow(n0); addrow(n1); addrow(n2); addrow(n3);
    }
    for (; j < e; j++) addrow(col[j]);

#pragma unroll
    for (int v = 0; v < P; v += 4)
        *(float4*)&out[(size_t)gw * HD + lane * P + v] =
            make_float4(acc[v], acc[v + 1], acc[v + 2], acc[v + 3]);
}

// ---------------- tf32 tensor-core GEMM ----------------
// C = epilogue(A[M,K] @ W[K,Nn] + bias); optional bf16 dual-write to Cb.

#define ASTRIDE 20
#define BSTRIDE 132

__device__ __forceinline__ uint32_t f2tf32(float x) {
    uint32_t r;
    asm("cvt.rna.tf32.f32 %0, %1;" : "=r"(r) : "f"(x));
    return r;
}

__device__ __forceinline__ void mma_tf32(float c[4], const uint32_t a[4], const uint32_t b[2]) {
    asm volatile(
        "mma.sync.aligned.m16n8k8.row.col.f32.tf32.tf32.f32 "
        "{%0,%1,%2,%3}, {%4,%5,%6,%7}, {%8,%9}, {%0,%1,%2,%3};\n"
        : "+f"(c[0]), "+f"(c[1]), "+f"(c[2]), "+f"(c[3])
        : "r"(a[0]), "r"(a[1]), "r"(a[2]), "r"(a[3]), "r"(b[0]), "r"(b[1]));
}

#define CP_ASYNC16(dst_u32, src_ptr, sz) \
    asm volatile("cp.async.cg.shared.global [%0], [%1], 16, %2;\n" \
                 :: "r"(dst_u32), "l"(src_ptr), "r"(sz))

template <bool DO_BN>
__global__ void __launch_bounds__(256) gemm_tc_kernel(
    const float* __restrict__ A, const float* __restrict__ W,
    const float* __restrict__ bias, float* __restrict__ C,
    __nv_bfloat16* __restrict__ Cb,
    int M, int K, int Nn,
    const float* __restrict__ bn_g, const float* __restrict__ bn_b,
    const float* __restrict__ bn_rm, const float* __restrict__ bn_rv)
{
    __shared__ float As[2][128 * ASTRIDE];
    __shared__ float Bs[2][16 * BSTRIDE];

    const int tid = threadIdx.x;
    const int lane = tid & 31;
    const int wid = tid >> 5;
    const int wr = wid & 1;
    const int wc = wid >> 1;
    const int rowBlk = blockIdx.x * 128;
    const int colBlk = blockIdx.y * 128;
    const int nk = K >> 4;

    int aSmOff[2], aSz[2];
    const float* aPtr0[2];
    int bSmOff[2];
    const float* bPtr0[2];
#pragma unroll
    for (int s = 0; s < 2; s++) {
        int i = tid + s * 256;
        int ar = i >> 2, ac = (i & 3) * 4;
        aSmOff[s] = ar * ASTRIDE + ac;
        int grow = rowBlk + ar;
        bool v = grow < M;
        aSz[s] = v ? 16 : 0;
        aPtr0[s] = A + (size_t)(v ? grow : 0) * K + ac;

        int br = i >> 5, bc = (i & 31) * 4;
        bSmOff[s] = br * BSTRIDE + bc;
        bPtr0[s] = W + (size_t)br * Nn + colBlk + bc;
    }
    uint32_t asBase[2], bsBase[2];
#pragma unroll
    for (int b = 0; b < 2; b++) {
        asBase[b] = (uint32_t)__cvta_generic_to_shared(&As[b][0]);
        bsBase[b] = (uint32_t)__cvta_generic_to_shared(&Bs[b][0]);
    }

    float acc[4][4][4];
#pragma unroll
    for (int mt = 0; mt < 4; mt++)
#pragma unroll
        for (int nt = 0; nt < 4; nt++)
#pragma unroll
            for (int q = 0; q < 4; q++) acc[mt][nt][q] = 0.0f;

#pragma unroll
    for (int s = 0; s < 2; s++)
        CP_ASYNC16(asBase[0] + aSmOff[s] * 4, aPtr0[s], aSz[s]);
#pragma unroll
    for (int s = 0; s < 2; s++)
        CP_ASYNC16(bsBase[0] + bSmOff[s] * 4, bPtr0[s], 16);
    asm volatile("cp.async.commit_group;\n");

    for (int kb = 0; kb < nk; kb++) {
        int cur = kb & 1;
        if (kb + 1 < nk) {
            int nxt = cur ^ 1;
#pragma unroll
            for (int s = 0; s < 2; s++)
                CP_ASYNC16(asBase[nxt] + aSmOff[s] * 4, aPtr0[s] + (kb + 1) * 16, aSz[s]);
#pragma unroll
            for (int s = 0; s < 2; s++)
                CP_ASYNC16(bsBase[nxt] + bSmOff[s] * 4, bPtr0[s] + (size_t)(kb + 1) * 16 * Nn, 16);
            asm volatile("cp.async.commit_group;\n");
            asm volatile("cp.async.wait_group 1;\n");
        } else {
            asm volatile("cp.async.wait_group 0;\n");
        }
        __syncthreads();

        const float* as = &As[cur][0];
        const float* bs = &Bs[cur][0];
#pragma unroll
        for (int ks = 0; ks < 2; ks++) {
            uint32_t afr[4][4];
#pragma unroll
            for (int mt = 0; mt < 4; mt++) {
                int r0 = wr * 64 + mt * 16 + (lane >> 2);
                int c0 = ks * 8 + (lane & 3);
                afr[mt][0] = f2tf32(as[r0 * ASTRIDE + c0]);
                afr[mt][1] = f2tf32(as[(r0 + 8) * ASTRIDE + c0]);
                afr[mt][2] = f2tf32(as[r0 * ASTRIDE + c0 + 4]);
                afr[mt][3] = f2tf32(as[(r0 + 8) * ASTRIDE + c0 + 4]);
            }
            uint32_t bfr[4][2];
#pragma unroll
            for (int nt = 0; nt < 4; nt++) {
                int kk = ks * 8 + (lane & 3);
                int cn = wc * 32 + nt * 8 + (lane >> 2);
                bfr[nt][0] = f2tf32(bs[kk * BSTRIDE + cn]);
                bfr[nt][1] = f2tf32(bs[(kk + 4) * BSTRIDE + cn]);
            }
#pragma unroll
            for (int mt = 0; mt < 4; mt++)
#pragma unroll
                for (int nt = 0; nt < 4; nt++)
                    mma_tf32(acc[mt][nt], afr[mt], bfr[nt]);
        }
        __syncthreads();
    }

    // ---- epilogue: bias + relu (+ BN), write C (+ bf16 shadow Cb) ----
#pragma unroll
    for (int nt = 0; nt < 4; nt++) {
        int c0 = colBlk + wc * 32 + nt * 8 + 2 * (lane & 3);
        float bb0 = bias[c0], bb1 = bias[c0 + 1];
        float s0 = 0.f, s1 = 0.f, m0 = 0.f, m1 = 0.f, e0 = 0.f, e1 = 0.f;
        if (DO_BN) {
            s0 = bn_g[c0] * rsqrtf(bn_rv[c0] + BN_EPS);
            s1 = bn_g[c0 + 1] * rsqrtf(bn_rv[c0 + 1] + BN_EPS);
            m0 = bn_rm[c0]; m1 = bn_rm[c0 + 1];
            e0 = bn_b[c0];  e1 = bn_b[c0 + 1];
        }
#pragma unroll
        for (int mt = 0; mt < 4; mt++) {
            int r = rowBlk + wr * 64 + mt * 16 + (lane >> 2);
            float v0 = fmaxf(acc[mt][nt][0] + bb0, 0.0f);
            float v1 = fmaxf(acc[mt][nt][1] + bb1, 0.0f);
            float v2 = fmaxf(acc[mt][nt][2] + bb0, 0.0f);
            float v3 = fmaxf(acc[mt][nt][3] + bb1, 0.0f);
            if (DO_BN) {
                v0 = (v0 - m0) * s0 + e0;
                v1 = (v1 - m1) * s1 + e1;
                v2 = (v2 - m0) * s0 + e0;
                v3 = (v3 - m1) * s1 + e1;
            }
            if (r < M) {
                *(float2*)&C[(size_t)r * Nn + c0] = make_float2(v0, v1);
                if (Cb) *(__nv_bfloat162*)&Cb[(size_t)r * Nn + c0] = __floats2bfloat162_rn(v0, v1);
            }
            if (r + 8 < M) {
                *(float2*)&C[(size_t)(r + 8) * Nn + c0] = make_float2(v2, v3);
                if (Cb) *(__nv_bfloat162*)&Cb[(size_t)(r + 8) * Nn + c0] = __floats2bfloat162_rn(v2, v3);
            }
        }
    }
}

// ---------------- pooling ----------------
#define NODES_PER_BLK 64
__global__ void pool_kernel(const float* __restrict__ h, const int* __restrict__ batch,
                            float* __restrict__ pooled, float* __restrict__ counts) {
    int c = threadIdx.x;
    int n0 = blockIdx.x * NODES_PER_BLK;
    float sum = 0.0f;
    int cur = -1;
    for (int i = 0; i < NODES_PER_BLK; i++) {
        int n = n0 + i;
        if (n >= NN) break;
        int g = batch[n];
        if (g != cur) {
            if (cur >= 0) atomicAdd(&pooled[(size_t)cur * HH + c], sum);
            sum = 0.0f;
            cur = g;
        }
        sum += h[(size_t)n * HH + c];
    }
    if (cur >= 0) atomicAdd(&pooled[(size_t)cur * HH + c], sum);

    if (c == 0) {
        float cnt = 0.0f;
        int cg = -1;
        for (int i = 0; i < NODES_PER_BLK; i++) {
            int n = n0 + i;
            if (n >= NN) break;
            int g = batch[n];
            if (g != cg) {
                if (cg >= 0) atomicAdd(&counts[cg], cnt);
                cnt = 0.0f;
                cg = g;
            }
            cnt += 1.0f;
        }
        if (cg >= 0) atomicAdd(&counts[cg], cnt);
    }
}

// ---------------- head ----------------
__global__ void head_kernel(const float* __restrict__ pooled, const float* __restrict__ counts,
                            const float* __restrict__ Wf, const float* __restrict__ bf,
                            const float* __restrict__ Wo, const float* __restrict__ bo,
                            float* __restrict__ out) {
    __shared__ float sp[HH];
    __shared__ float sh[HH];
    __shared__ float sl[CC];
    int g = blockIdx.x;
    int t = threadIdx.x;
    float cnt = fmaxf(counts[g], 1.0f);
    sp[t] = pooled[(size_t)g * HH + t] / cnt;
    __syncthreads();
    float acc = bf[t];
#pragma unroll 8
    for (int k = 0; k < HH; k++)
        acc = fmaf(sp[k], Wf[(size_t)k * HH + t], acc);
    sh[t] = fmaxf(acc, 0.0f);
    __syncthreads();
    if (t < CC) {
        float a = bo[t];
        for (int k = 0; k < HH; k++)
            a = fmaf(sh[k], Wo[(size_t)k * CC + t], a);
        sl[t] = a;
    }
    __syncthreads();
    if (t == 0) {
        float mx = -1e30f;
        for (int c = 0; c < CC; c++) mx = fmaxf(mx, sl[c]);
        float s = 0.0f;
        for (int c = 0; c < CC; c++) s += expf(sl[c] - mx);
        float lse = mx + logf(s);
        for (int c = 0; c < CC; c++) out[(size_t)g * CC + c] = sl[c] - lse;
    }
}

// ---------------- launch ----------------
extern "C" void kernel_launch(void* const* d_in, const int* in_sizes, int n_in,
                              void* d_out, int out_size) {
    const float* x    = (const float*)d_in[0];
    const int*   ei   = (const int*)d_in[1];
    const int*   src  = ei;
    const int*   dst  = ei + EE;
    const int*   batch= (const int*)d_in[2];
    const float* W1a  = (const float*)d_in[3];
    const float* b1a  = (const float*)d_in[4];
    const float* W2a  = (const float*)d_in[5];
    const float* b2a  = (const float*)d_in[6];
    const float* g_a  = (const float*)d_in[7];
    const float* be_a = (const float*)d_in[8];
    const float* rm_a = (const float*)d_in[9];
    const float* rv_a = (const float*)d_in[10];
    const float* Ws1  = (const float*)d_in[11];
    const float* bs1  = (const float*)d_in[12];
    const float* Ws2  = (const float*)d_in[13];
    const float* bs2  = (const float*)d_in[14];
    const float* gs   = (const float*)d_in[15];
    const float* bes  = (const float*)d_in[16];
    const float* rms  = (const float*)d_in[17];
    const float* rvs  = (const float*)d_in[18];
    const float* Wf   = (const float*)d_in[19];
    const float* bf   = (const float*)d_in[20];
    const float* Wo   = (const float*)d_in[21];
    const float* bo   = (const float*)d_in[22];
    float* out = (float*)d_out;

    float *bufQ, *bufR, *bufP, *pooled, *counts;
    __nv_bfloat16* bufB;
    int *rowptr, *col, *deg, *bsum;
    cudaGetSymbolAddress((void**)&bufQ, g_bufQ);
    cudaGetSymbolAddress((void**)&bufR, g_bufR);
    cudaGetSymbolAddress((void**)&bufP, g_bufP);
    cudaGetSymbolAddress((void**)&bufB, g_bufB);
    cudaGetSymbolAddress((void**)&rowptr, g_rowptr);
    cudaGetSymbolAddress((void**)&col, g_col);
    cudaGetSymbolAddress((void**)&deg, g_deg);
    cudaGetSymbolAddress((void**)&bsum, g_bsum);
    cudaGetSymbolAddress((void**)&pooled, g_pooled);
    cudaGetSymbolAddress((void**)&counts, g_counts);

    const int NB = (NN + 1023) / 1024;

    // ---- CSR build ----
    zero_i_kernel<<<(NN + 255) / 256, 256>>>(deg, NN);
    count_kernel<<<(EE + 255) / 256, 256>>>(dst, deg);
    scan1_kernel<<<NB, 1024>>>(deg, rowptr, bsum);
    scan2_kernel<<<1, 128>>>(bsum, NB);
    scan3_kernel<<<NB, 1024>>>(rowptr, bsum);
    zero_i_kernel<<<(NN + 255) / 256, 256>>>(deg, NN);
    fill_kernel<<<(EE + 255) / 256, 256>>>(src, dst, rowptr, deg, col);

    dim3 ggrid((NN + 127) / 128, HH / 128);
    const int aggBlocks = (NN * 32 + 255) / 256;

    // ---- layer 1 (F=128 -> H=256) ----
    f2b_kernel<<<(NN * FF / 4 + 255) / 256, 256>>>(x, bufB, NN * FF / 4);
    aggb_kernel<FF><<<aggBlocks, 256>>>(x, bufB, bufQ, rowptr, col);
    gemm_tc_kernel<false><<<ggrid, 256>>>(bufQ, W1a, b1a, bufR, nullptr, NN, FF, HH,
                                          nullptr, nullptr, nullptr, nullptr);
    gemm_tc_kernel<true><<<ggrid, 256>>>(bufR, W2a, b2a, bufP, bufB, NN, HH, HH,
                                         g_a, be_a, rm_a, rv_a);

    // ---- layers 2..4 ----
    for (int l = 0; l < L_REST; l++) {
        aggb_kernel<HH><<<aggBlocks, 256>>>(bufP, bufB, bufQ, rowptr, col);
        gemm_tc_kernel<false><<<ggrid, 256>>>(bufQ, Ws1 + (size_t)l * HH * HH, bs1 + l * HH,
                                              bufR, nullptr, NN, HH, HH,
                                              nullptr, nullptr, nullptr, nullptr);
        gemm_tc_kernel<true><<<ggrid, 256>>>(bufR, Ws2 + (size_t)l * HH * HH, bs2 + l * HH,
                                             bufP, (l < L_REST - 1) ? bufB : nullptr, NN, HH, HH,
                                             gs + l * HH, bes + l * HH, rms + l * HH, rvs + l * HH);
    }

    // ---- pooling ----
    zero_f_kernel<<<(GG * HH + 255) / 256, 256>>>(pooled, GG * HH);
    zero_f_kernel<<<(GG + 255) / 256, 256>>>(counts, GG);
    pool_kernel<<<(NN + NODES_PER_BLK - 1) / NODES_PER_BLK, HH>>>(bufP, batch, pooled, counts);

    // ---- head ----
    head_kernel<<<GG, HH>>>(pooled, counts, Wf, bf, Wo, bo, out);
}